// round 1
// baseline (speedup 1.0000x reference)
#include <cuda_runtime.h>

#define F_TOTAL 256
#define H 16
#define BATCH 32768
#define GF 16                    // features per CTA
#define NGROUPS (F_TOTAL / GF)   // 16
#define TPB 256

// ---- f32x2 packed helpers (sm_103a) ----
__device__ __forceinline__ unsigned long long pack2(float lo, float hi) {
    unsigned long long r;
    asm("mov.b64 %0, {%1, %2};" : "=l"(r)
        : "r"(__float_as_uint(lo)), "r"(__float_as_uint(hi)));
    return r;
}
__device__ __forceinline__ unsigned long long bcast2(float v) {
    unsigned long long r;
    unsigned u = __float_as_uint(v);
    asm("mov.b64 %0, {%1, %1};" : "=l"(r) : "r"(u));
    return r;
}
__device__ __forceinline__ void ffma2(unsigned long long& d,
                                      unsigned long long a,
                                      unsigned long long b) {
    asm("fma.rn.f32x2 %0, %1, %2, %0;" : "+l"(d) : "l"(a), "l"(b));
}
__device__ __forceinline__ float lo32(unsigned long long v) {
    return __uint_as_float((unsigned)v);
}
__device__ __forceinline__ float hi32(unsigned long long v) {
    return __uint_as_float((unsigned)(v >> 32));
}

__global__ void igann_init_kernel(float* __restrict__ out,
                                  const float* __restrict__ bias_b) {
    int i = blockIdx.x * blockDim.x + threadIdx.x;
    if (i < BATCH) out[i] = bias_b[0];
}

__global__ __launch_bounds__(TPB) void igann_kernel(
    const float* __restrict__ x,   // [B, F]
    const float* __restrict__ la,  // [F]
    const float* __restrict__ W1,  // [F, H]
    const float* __restrict__ b1,  // [F, H]
    const float* __restrict__ W2,  // [F, H(out j), H(in i)]
    const float* __restrict__ b2,  // [F, H]
    const float* __restrict__ W3,  // [F, H]
    const float* __restrict__ b3,  // [F]
    float* __restrict__ out)       // [B]
{
    // Shared staging for this CTA's 16 features
    __shared__ float sW1[GF * H];          // 1 KB
    __shared__ float sB1[GF * H];          // 1 KB
    // (fi, i, q): .x = {W2[f][4q][i],   W2[f][4q+1][i]}
    //             .y = {W2[f][4q+2][i], W2[f][4q+3][i]}
    __shared__ ulonglong2 sW2[GF * H * 4]; // 16 KB
    __shared__ ulonglong2 sB2[GF * 4];     // raw b2 rows, pair-aliased (256 B)
    __shared__ ulonglong2 sW3[GF * 4];     // raw W3 rows, pair-aliased (256 B)
    __shared__ float sB3[GF];
    __shared__ float sA[GF];

    const int g   = blockIdx.y;
    const int tid = threadIdx.x;
    const int f0  = g * GF;

    // --- stage weights ---
    // W1/b1/b2/W3 rows for features f0..f0+15 are contiguous (GF*H == TPB)
    sW1[tid] = W1[f0 * H + tid];
    sB1[tid] = b1[f0 * H + tid];
    ((float*)sB2)[tid] = b2[f0 * H + tid];
    ((float*)sW3)[tid] = W3[f0 * H + tid];
    if (tid < GF) {
        sB3[tid] = b3[f0 + tid];
        sA[tid]  = la[f0 + tid];
    }
    // W2: transpose + pair-pack along output dim j
    #pragma unroll
    for (int k = 0; k < 4; k++) {
        int e  = tid + k * TPB;        // 0..1023
        int fi = e >> 6;
        int i  = (e >> 2) & 15;
        int q  = e & 3;
        const float* wp = W2 + (size_t)(f0 + fi) * (H * H) + i;
        float a0 = wp[(4 * q + 0) * H];
        float a1 = wp[(4 * q + 1) * H];
        float a2 = wp[(4 * q + 2) * H];
        float a3 = wp[(4 * q + 3) * H];
        ulonglong2 v;
        v.x = pack2(a0, a1);
        v.y = pack2(a2, a3);
        sW2[e] = v;
    }
    __syncthreads();

    // --- compute: one batch row per thread ---
    const int b = blockIdx.x * TPB + tid;
    const float4* xrow = (const float4*)(x + (size_t)b * F_TOTAL + f0);

    float accs = 0.f;
    unsigned long long accq0 = 0ull, accq1 = 0ull;

    #pragma unroll 1            // keep code size inside I$ (4-feature body)
    for (int o = 0; o < 4; o++) {
        float4 xq = xrow[o];
        #pragma unroll
        for (int u = 0; u < 4; u++) {
            const int fi = o * 4 + u;
            const float xv = (u == 0) ? xq.x : (u == 1) ? xq.y
                           : (u == 2) ? xq.z : xq.w;

            // init h2 accumulators with b2 (bit-aliased pairs)
            unsigned long long acc[8];
            #pragma unroll
            for (int q = 0; q < 4; q++) {
                ulonglong2 bv = sB2[fi * 4 + q];
                acc[2 * q]     = bv.x;
                acc[2 * q + 1] = bv.y;
            }

            const ulonglong2* wrow = &sW2[fi * (H * 4)];
            #pragma unroll
            for (int i = 0; i < H; i++) {
                float h1 = fmaxf(fmaf(xv, sW1[fi * H + i], sB1[fi * H + i]), 0.f);
                unsigned long long hb = bcast2(h1);
                #pragma unroll
                for (int q = 0; q < 4; q++) {
                    ulonglong2 w = wrow[i * 4 + q];
                    ffma2(acc[2 * q],     w.x, hb);
                    ffma2(acc[2 * q + 1], w.y, hb);
                }
            }

            // relu(h2) then fc3 (packed), two alternating accumulators
            #pragma unroll
            for (int q = 0; q < 4; q++) {
                ulonglong2 w3 = sW3[fi * 4 + q];
                unsigned long long hp0 =
                    pack2(fmaxf(lo32(acc[2 * q]), 0.f),
                          fmaxf(hi32(acc[2 * q]), 0.f));
                unsigned long long hp1 =
                    pack2(fmaxf(lo32(acc[2 * q + 1]), 0.f),
                          fmaxf(hi32(acc[2 * q + 1]), 0.f));
                if (q & 1) { ffma2(accq1, hp0, w3.x); ffma2(accq1, hp1, w3.y); }
                else       { ffma2(accq0, hp0, w3.x); ffma2(accq0, hp1, w3.y); }
            }

            // linear term + per-feature output bias
            accs = fmaf(sA[fi], xv, accs + sB3[fi]);
        }
    }

    float res = accs + lo32(accq0) + hi32(accq0) + lo32(accq1) + hi32(accq1);
    atomicAdd(&out[b], res);
}

extern "C" void kernel_launch(void* const* d_in, const int* in_sizes, int n_in,
                              void* d_out, int out_size) {
    const float* x      = (const float*)d_in[0];
    const float* la     = (const float*)d_in[1];
    const float* bias_b = (const float*)d_in[2];
    const float* W1     = (const float*)d_in[3];
    const float* b1     = (const float*)d_in[4];
    const float* W2     = (const float*)d_in[5];
    const float* b2     = (const float*)d_in[6];
    const float* W3     = (const float*)d_in[7];
    const float* b3     = (const float*)d_in[8];
    float* out = (float*)d_out;

    igann_init_kernel<<<BATCH / 256, 256>>>(out, bias_b);

    dim3 grid(BATCH / TPB, NGROUPS);
    igann_kernel<<<grid, TPB>>>(x, la, W1, b1, W2, b2, W3, b3, out);
}

// round 2
// speedup vs baseline: 1.5555x; 1.5555x over previous
#include <cuda_runtime.h>

#define F_TOTAL 256
#define H 16
#define BATCH 32768
#define GF 16                    // features per CTA
#define NGROUPS (F_TOTAL / GF)   // 16
#define TPB 128
#define RB 4                     // batch rows per thread

// ---- f32x2 packed helpers (sm_103a) ----
__device__ __forceinline__ unsigned long long pack2(float lo, float hi) {
    unsigned long long r;
    asm("mov.b64 %0, {%1, %2};" : "=l"(r)
        : "r"(__float_as_uint(lo)), "r"(__float_as_uint(hi)));
    return r;
}
__device__ __forceinline__ unsigned long long bcast2(float v) {
    unsigned long long r;
    unsigned u = __float_as_uint(v);
    asm("mov.b64 %0, {%1, %1};" : "=l"(r) : "r"(u));
    return r;
}
__device__ __forceinline__ void ffma2(unsigned long long& d,
                                      unsigned long long a,
                                      unsigned long long b) {
    asm("fma.rn.f32x2 %0, %1, %2, %0;" : "+l"(d) : "l"(a), "l"(b));
}
__device__ __forceinline__ float lo32(unsigned long long v) {
    return __uint_as_float((unsigned)v);
}
__device__ __forceinline__ float hi32(unsigned long long v) {
    return __uint_as_float((unsigned)(v >> 32));
}

__global__ void igann_init_kernel(float* __restrict__ out,
                                  const float* __restrict__ bias_b) {
    int i = blockIdx.x * blockDim.x + threadIdx.x;
    if (i < BATCH) out[i] = bias_b[0];
}

__global__ __launch_bounds__(TPB) void igann_kernel(
    const float* __restrict__ x,   // [B, F]
    const float* __restrict__ la,  // [F]
    const float* __restrict__ W1,  // [F, H]
    const float* __restrict__ b1,  // [F, H]
    const float* __restrict__ W2,  // [F, H(out j), H(in i)]
    const float* __restrict__ b2,  // [F, H]
    const float* __restrict__ W3,  // [F, H]
    const float* __restrict__ b3,  // [F]
    float* __restrict__ out)       // [B]
{
    __shared__ float2 sW1B1[GF * H];       // (w1, b1) fused, 2 KB
    __shared__ ulonglong2 sW2[GF * H * 4]; // j-pair-packed W2^T, 16 KB
    __shared__ ulonglong2 sB2[GF * 4];     // raw b2 rows, pair-aliased
    __shared__ float sW3s[GF * H];
    __shared__ float sB3[GF];
    __shared__ float sA[GF];

    const int g   = blockIdx.y;
    const int tid = threadIdx.x;
    const int f0  = g * GF;

    // --- stage weights ---
    #pragma unroll
    for (int k = 0; k < 2; k++) {
        int idx = tid + k * TPB;   // 0..255 == GF*H
        sW1B1[idx] = make_float2(W1[f0 * H + idx], b1[f0 * H + idx]);
        ((float*)sB2)[idx] = b2[f0 * H + idx];
        sW3s[idx] = W3[f0 * H + idx];
    }
    if (tid < GF) {
        sB3[tid] = b3[f0 + tid];
        sA[tid]  = la[f0 + tid];
    }
    // W2: transpose + pair-pack along output dim j
    #pragma unroll
    for (int k = 0; k < 8; k++) {
        int e  = tid + k * TPB;    // 0..1023
        int fi = e >> 6;
        int i  = (e >> 2) & 15;
        int q  = e & 3;
        const float* wp = W2 + (size_t)(f0 + fi) * (H * H) + i;
        ulonglong2 v;
        v.x = pack2(wp[(4 * q + 0) * H], wp[(4 * q + 1) * H]);
        v.y = pack2(wp[(4 * q + 2) * H], wp[(4 * q + 3) * H]);
        sW2[e] = v;
    }
    __syncthreads();

    // --- compute: RB batch rows per thread ---
    const int b0 = blockIdx.x * (TPB * RB) + tid;

    float oA[RB], oB[RB];
    #pragma unroll
    for (int r = 0; r < RB; r++) { oA[r] = 0.f; oB[r] = 0.f; }

    #pragma unroll 1
    for (int oc = 0; oc < 4; oc++) {
        float4 xq[RB];
        #pragma unroll
        for (int r = 0; r < RB; r++)
            xq[r] = *(const float4*)(x + (size_t)(b0 + r * TPB) * F_TOTAL
                                       + f0 + oc * 4);

        #pragma unroll
        for (int u = 0; u < 4; u++) {
            const int fi = oc * 4 + u;
            float xv[RB];
            #pragma unroll
            for (int r = 0; r < RB; r++)
                xv[r] = (u == 0) ? xq[r].x : (u == 1) ? xq[r].y
                      : (u == 2) ? xq[r].z : xq[r].w;

            // init h2 accumulators with b2 (bit-aliased pairs)
            unsigned long long acc[RB][8];
            #pragma unroll
            for (int q = 0; q < 4; q++) {
                ulonglong2 bv = sB2[fi * 4 + q];
                #pragma unroll
                for (int r = 0; r < RB; r++) {
                    acc[r][2 * q]     = bv.x;
                    acc[r][2 * q + 1] = bv.y;
                }
            }

            const ulonglong2* wrow = &sW2[fi * (H * 4)];
            const float2*     wb1  = &sW1B1[fi * H];
            #pragma unroll 4
            for (int i = 0; i < H; i++) {
                float2 wb = wb1[i];                 // one LDS.64, RB rows
                unsigned long long hb[RB];
                #pragma unroll
                for (int r = 0; r < RB; r++)
                    hb[r] = bcast2(fmaxf(fmaf(xv[r], wb.x, wb.y), 0.f));
                #pragma unroll
                for (int q = 0; q < 4; q++) {
                    ulonglong2 w = wrow[i * 4 + q]; // one LDS.128, 2*RB ffma2
                    #pragma unroll
                    for (int r = 0; r < RB; r++) {
                        ffma2(acc[r][2 * q],     w.x, hb[r]);
                        ffma2(acc[r][2 * q + 1], w.y, hb[r]);
                    }
                }
            }

            // fc3 epilogue: relu(h2) . W3, two alternating accumulators
            const float4* w3p = (const float4*)&sW3s[fi * H];
            #pragma unroll
            for (int k4 = 0; k4 < 4; k4++) {
                float4 w3 = w3p[k4];
                #pragma unroll
                for (int r = 0; r < RB; r++) {
                    unsigned long long a0 = acc[r][2 * k4];
                    unsigned long long a1 = acc[r][2 * k4 + 1];
                    float* op = (k4 & 1) ? &oB[r] : &oA[r];
                    float t = *op;
                    t = fmaf(fmaxf(lo32(a0), 0.f), w3.x, t);
                    t = fmaf(fmaxf(hi32(a0), 0.f), w3.y, t);
                    t = fmaf(fmaxf(lo32(a1), 0.f), w3.z, t);
                    t = fmaf(fmaxf(hi32(a1), 0.f), w3.w, t);
                    *op = t;
                }
            }
            // linear term + per-feature output bias
            #pragma unroll
            for (int r = 0; r < RB; r++)
                oA[r] = fmaf(sA[fi], xv[r], oA[r] + sB3[fi]);
        }
    }

    #pragma unroll
    for (int r = 0; r < RB; r++)
        atomicAdd(&out[b0 + r * TPB], oA[r] + oB[r]);
}

extern "C" void kernel_launch(void* const* d_in, const int* in_sizes, int n_in,
                              void* d_out, int out_size) {
    const float* x      = (const float*)d_in[0];
    const float* la     = (const float*)d_in[1];
    const float* bias_b = (const float*)d_in[2];
    const float* W1     = (const float*)d_in[3];
    const float* b1     = (const float*)d_in[4];
    const float* W2     = (const float*)d_in[5];
    const float* b2     = (const float*)d_in[6];
    const float* W3     = (const float*)d_in[7];
    const float* b3     = (const float*)d_in[8];
    float* out = (float*)d_out;

    igann_init_kernel<<<BATCH / 256, 256>>>(out, bias_b);

    dim3 grid(BATCH / (TPB * RB), NGROUPS);
    igann_kernel<<<grid, TPB>>>(x, la, W1, b1, W2, b2, W3, b3, out);
}